// round 5
// baseline (speedup 1.0000x reference)
#include <cuda_runtime.h>
#include <cstdint>

// ============================================================================
// MaxMarginLoss on GB300 (compute_103 baseline ISA):
//  - e4m3 FP8 HMMA (mma.sync m16n8k32) candidate-ranking GEMM, persistent-A
//    smem tiling, fused streaming per-tile top-2
//  - exact fp32 rescore of global top-4 candidates per row
//   input  (4096, 512) f32 | target (4096, 512) f32 | veclist (50000, 512) f32
//   out: scalar f32
// ============================================================================

#define EPSF 1e-8f
#define GAMMAF 0.5f

#define B_DIM 4096
#define D_DIM 512
#define V_DIM 50000
#define M_TILE 256
#define N_TILE 128
#define NUM_VT 392                  // ceil(50000/128); 392*128 = 50176
#define V_PAD (NUM_VT * N_TILE)
#define NUM_KC 4                    // 512 / 128 fp8 elems per chunk
#define K_CHUNK 128                 // fp8 elems per chunk = 128 B rows (SW128)
#define M_BLOCKS (B_DIM / M_TILE)   // 16
#define V_GROUPS 9                  // 16*9 = 144 CTAs = one wave
#define TILES_PER_GROUP 44          // 8*44 + 40 = 392
#define FP8_SCALE 32.0f

// smem layout (bytes)
#define SMEM_A_OFF 0                // 4 chunks x 32 KB = 128 KB (persistent A)
#define SMEM_B_OFF 131072           // 2 bufs x 16 KB = 32 KB
#define SMEM_STG_OFF 163840         // 256 rows x 2 x 16 B = 8 KB
#define SMEM_TOTAL 172032

// ---------------- scratch (device globals; no allocation allowed) -----------
struct Top2 { float v0; int i0; float v1; int i1; };

__device__ __align__(16) uint8_t g_inn8[(size_t)B_DIM * D_DIM];        // 2 MB
__device__ __align__(16) uint8_t g_vnn8[(size_t)V_PAD * D_DIM];        // 25.7 MB
__device__ float g_dpos[B_DIM];
__device__ float g_norm_in[B_DIM];
__device__ __align__(16) Top2 g_part[(size_t)NUM_VT * B_DIM];          // 25.7 MB
__device__ float g_margin[B_DIM];

// ---------------- helpers ----------------------------------------------------
#define SWZ(o) ((o) ^ (((o) >> 3) & 0x70))

__device__ __forceinline__ uint32_t smem_u32(const void* p) {
    return (uint32_t)__cvta_generic_to_shared(p);
}

__device__ __forceinline__ void cp16(uint32_t s, const void* g) {
    asm volatile("cp.async.cg.shared.global [%0], [%1], 16;" :: "r"(s), "l"(g));
}

__device__ __forceinline__ void ldmatrix_x4(uint32_t* r, uint32_t addr) {
    asm volatile("ldmatrix.sync.aligned.m8n8.x4.shared.b16 {%0,%1,%2,%3}, [%4];"
                 : "=r"(r[0]), "=r"(r[1]), "=r"(r[2]), "=r"(r[3]) : "r"(addr));
}

__device__ __forceinline__ void mma16832(float* d, const uint32_t* a,
                                         uint32_t b0, uint32_t b1) {
    asm volatile(
        "mma.sync.aligned.m16n8k32.row.col.f32.e4m3.e4m3.f32 "
        "{%0,%1,%2,%3}, {%4,%5,%6,%7}, {%8,%9}, {%0,%1,%2,%3};"
        : "+f"(d[0]), "+f"(d[1]), "+f"(d[2]), "+f"(d[3])
        : "r"(a[0]), "r"(a[1]), "r"(a[2]), "r"(a[3]), "r"(b0), "r"(b1));
}

// pack 2 floats -> e4m3x2 (lo byte = e0)
__device__ __forceinline__ uint16_t f2_to_e4m3x2(float e0, float e1) {
    uint16_t r;
    asm("cvt.rn.satfinite.e4m3x2.f32 %0, %1, %2;" : "=h"(r) : "f"(e1), "f"(e0));
    return r;
}

__device__ __forceinline__ void top2_insert(float c, int ci,
                                            float& v0, int& i0,
                                            float& v1, int& i1) {
    if (c > v0) { v1 = v0; i1 = i0; v0 = c; i0 = ci; }
    else if (c > v1) { v1 = c; i1 = ci; }
}

__device__ __forceinline__ void top4_insert(float c, int ci, float* v, int* ix) {
    if (c > v[3]) {
        if (c > v[1]) {
            if (c > v[0]) {
                v[3]=v[2]; ix[3]=ix[2]; v[2]=v[1]; ix[2]=ix[1];
                v[1]=v[0]; ix[1]=ix[0]; v[0]=c; ix[0]=ci;
            } else {
                v[3]=v[2]; ix[3]=ix[2]; v[2]=v[1]; ix[2]=ix[1];
                v[1]=c; ix[1]=ci;
            }
        } else {
            if (c > v[2]) { v[3]=v[2]; ix[3]=ix[2]; v[2]=c; ix[2]=ci; }
            else { v[3]=c; ix[3]=ci; }
        }
    }
}

// ---------------- kernel 1: normalize input rows (fp8), d_pos ---------------
__global__ __launch_bounds__(128) void prep_input_kernel(
    const float* __restrict__ input, const float* __restrict__ target) {
    const int row = blockIdx.x;
    const int tid = threadIdx.x;

    const float4* x4 = reinterpret_cast<const float4*>(input + (size_t)row * D_DIM);
    const float4* t4 = reinterpret_cast<const float4*>(target + (size_t)row * D_DIM);
    float4 xv = x4[tid];
    float4 tv = t4[tid];
    float sxx = xv.x*xv.x + xv.y*xv.y + xv.z*xv.z + xv.w*xv.w;
    float stt = tv.x*tv.x + tv.y*tv.y + tv.z*tv.z + tv.w*tv.w;
    float sxt = xv.x*tv.x + xv.y*tv.y + xv.z*tv.z + xv.w*tv.w;

    #pragma unroll
    for (int o = 16; o > 0; o >>= 1) {
        sxx += __shfl_xor_sync(0xFFFFFFFFu, sxx, o);
        stt += __shfl_xor_sync(0xFFFFFFFFu, stt, o);
        sxt += __shfl_xor_sync(0xFFFFFFFFu, sxt, o);
    }
    __shared__ float red[12];
    const int w = tid >> 5;
    if ((tid & 31) == 0) { red[w] = sxx; red[4 + w] = stt; red[8 + w] = sxt; }
    __syncthreads();
    sxx = red[0] + red[1] + red[2] + red[3];
    stt = red[4] + red[5] + red[6] + red[7];
    sxt = red[8] + red[9] + red[10] + red[11];

    const float nx = fmaxf(sqrtf(sxx), EPSF);
    const float nt = fmaxf(sqrtf(stt), EPSF);
    const float inv = FP8_SCALE / nx;

    uint16_t lo = f2_to_e4m3x2(xv.x * inv, xv.y * inv);
    uint16_t hi = f2_to_e4m3x2(xv.z * inv, xv.w * inv);
    reinterpret_cast<uint32_t*>(g_inn8 + (size_t)row * D_DIM)[tid] =
        (uint32_t)lo | ((uint32_t)hi << 16);

    if (tid == 0) {
        float sim = sxt / (nx * nt);
        g_dpos[row] = sqrtf(fmaxf(2.0f * (1.0f - sim), 1e-12f));
        g_norm_in[row] = nx;
    }
}

// ---------------- kernel 2: normalize veclist rows (fp8), zero-pad ----------
__global__ __launch_bounds__(128) void prep_vec_kernel(const float* __restrict__ veclist) {
    const int row = blockIdx.x;
    const int tid = threadIdx.x;
    uint32_t* dst = reinterpret_cast<uint32_t*>(g_vnn8 + (size_t)row * D_DIM);

    if (row >= V_DIM) { dst[tid] = 0u; return; }

    const float4* v4 = reinterpret_cast<const float4*>(veclist + (size_t)row * D_DIM);
    float4 vv = v4[tid];
    float s = vv.x*vv.x + vv.y*vv.y + vv.z*vv.z + vv.w*vv.w;
    #pragma unroll
    for (int o = 16; o > 0; o >>= 1) s += __shfl_xor_sync(0xFFFFFFFFu, s, o);
    __shared__ float red[4];
    const int w = tid >> 5;
    if ((tid & 31) == 0) red[w] = s;
    __syncthreads();
    s = red[0] + red[1] + red[2] + red[3];

    const float inv = FP8_SCALE / fmaxf(sqrtf(s), EPSF);
    uint16_t lo = f2_to_e4m3x2(vv.x * inv, vv.y * inv);
    uint16_t hi = f2_to_e4m3x2(vv.z * inv, vv.w * inv);
    dst[tid] = (uint32_t)lo | ((uint32_t)hi << 16);
}

// ---------------- kernel 3: fp8 HMMA GEMM, persistent A + fused top-2 -------
// Grid: (V_GROUPS, M_BLOCKS) = (9, 16) = 144 CTAs (one wave).
// CTA: A slice [256 x 512] fp8 resident in smem; streams its group's B tiles.
__global__ __launch_bounds__(512, 1) void gemm_top2_kernel() {
    extern __shared__ char smem[];
    const int tid  = threadIdx.x;
    const int wid  = tid >> 5;
    const int lane = tid & 31;
    const int warp_m = wid & 7;        // 8 warps over M (32 rows each)
    const int warp_n = wid >> 3;       // 2 warps over N (64 cols each)
    const int m0 = warp_m * 32;
    const int n0 = warp_n * 64;
    const int mbase = blockIdx.y * M_TILE;

    const int tile_start = blockIdx.x * TILES_PER_GROUP;
    const int tile_end   = min(tile_start + TILES_PER_GROUP, NUM_VT);
    const int n_work     = (tile_end - tile_start) * NUM_KC;

    const uint32_t sbase = smem_u32(smem);
    const uint32_t sStg  = sbase + SMEM_STG_OFF;

    const uint8_t* gA = g_inn8 + (size_t)mbase * D_DIM;

    // ---- load persistent A: 256 rows x 512 B, chunked 4 x (256 x 128B) ----
    #pragma unroll
    for (int t = 0; t < 16; t++) {
        int i = tid + t * 512;            // 8192 cp16 total
        int row = i >> 5;                 // 32 x 16B per row
        int q   = i & 31;
        uint32_t dst = sbase + SMEM_A_OFF + (uint32_t)(q >> 3) * 32768u
                     + SWZ((uint32_t)(row * 128 + (q & 7) * 16));
        cp16(dst, gA + (size_t)row * D_DIM + q * 16);
    }

    // B chunk loader: work index c -> tile (c>>2), k-chunk (c&3)
    auto load_B = [&](int buf, int c) {
        const int tile = tile_start + (c >> 2);
        const int kc   = c & 3;
        const uint8_t* src = g_vnn8 + (size_t)tile * N_TILE * D_DIM + kc * K_CHUNK;
        const uint32_t sB = sbase + SMEM_B_OFF + (uint32_t)buf * 16384u;
        #pragma unroll
        for (int t = 0; t < 2; t++) {
            int i = tid + t * 512;        // 1024 cp16 total
            int row = i >> 3, q = i & 7;
            cp16(sB + SWZ((uint32_t)(row * 128 + q * 16)),
                 src + (size_t)row * D_DIM + q * 16);
        }
    };

    load_B(0, 0);
    asm volatile("cp.async.commit_group;" ::: "memory");   // group0 = A + B(0)

    float acc[2][8][4];
    #pragma unroll
    for (int mt = 0; mt < 2; mt++)
        #pragma unroll
        for (int nt = 0; nt < 8; nt++)
            #pragma unroll
            for (int cc = 0; cc < 4; cc++) acc[mt][nt][cc] = 0.0f;

    const int lrow  = lane & 15;
    const int lkoff = (lane >> 4) * 16;

    for (int c = 0; c < n_work; c++) {
        if (c + 1 < n_work) {
            load_B((c + 1) & 1, c + 1);
            asm volatile("cp.async.commit_group;" ::: "memory");
            asm volatile("cp.async.wait_group 1;" ::: "memory");
        } else {
            asm volatile("cp.async.wait_group 0;" ::: "memory");
        }
        __syncthreads();

        const uint32_t sA = sbase + SMEM_A_OFF + (uint32_t)(c & 3) * 32768u;
        const uint32_t sB = sbase + SMEM_B_OFF + (uint32_t)(c & 1) * 16384u;

        #pragma unroll
        for (int s = 0; s < 4; s++) {        // 4 k32 steps per 128-B chunk
            uint32_t af[2][4];
            #pragma unroll
            for (int mt = 0; mt < 2; mt++) {
                uint32_t byte = (uint32_t)((m0 + mt * 16 + lrow) * 128 + s * 32 + lkoff);
                ldmatrix_x4(af[mt], sA + SWZ(byte));
            }
            #pragma unroll
            for (int p = 0; p < 4; p++) {    // 4 n16 pairs = 8 n8 tiles
                uint32_t bf[4];
                uint32_t byte = (uint32_t)((n0 + p * 16 + lrow) * 128 + s * 32 + lkoff);
                ldmatrix_x4(bf, sB + SWZ(byte));
                #pragma unroll
                for (int mt = 0; mt < 2; mt++) {
                    mma16832(acc[mt][2 * p],     af[mt], bf[0], bf[2]);
                    mma16832(acc[mt][2 * p + 1], af[mt], bf[1], bf[3]);
                }
            }
        }
        __syncthreads();

        if ((c & 3) == 3) {
            // ---- epilogue for finished tile: top-2 per row over 128 cols ----
            const int tile  = tile_start + (c >> 2);
            const int vbase = tile * N_TILE;
            Top2* stage = reinterpret_cast<Top2*>(smem + SMEM_STG_OFF);
            (void)sStg;

            #pragma unroll
            for (int mt = 0; mt < 2; mt++) {
                #pragma unroll
                for (int h = 0; h < 2; h++) {
                    float v0 = -1e30f, v1 = -1e30f;
                    int   i0 = -1, i1 = -1;
                    #pragma unroll
                    for (int nt = 0; nt < 8; nt++) {
                        #pragma unroll
                        for (int cc = 0; cc < 2; cc++) {
                            int col = vbase + n0 + nt * 8 + 2 * (lane & 3) + cc;
                            float val = acc[mt][nt][2 * h + cc];
                            if (col < V_DIM) top2_insert(val, col, v0, i0, v1, i1);
                        }
                    }
                    #pragma unroll
                    for (int o = 1; o <= 2; o <<= 1) {
                        float w0 = __shfl_xor_sync(0xFFFFFFFFu, v0, o);
                        int   wi0 = __shfl_xor_sync(0xFFFFFFFFu, i0, o);
                        float w1 = __shfl_xor_sync(0xFFFFFFFFu, v1, o);
                        int   wi1 = __shfl_xor_sync(0xFFFFFFFFu, i1, o);
                        top2_insert(w0, wi0, v0, i0, v1, i1);
                        top2_insert(w1, wi1, v0, i0, v1, i1);
                    }
                    if ((lane & 3) == 0) {
                        int row_local = m0 + mt * 16 + h * 8 + (lane >> 2);
                        Top2 t; t.v0 = v0; t.i0 = i0; t.v1 = v1; t.i1 = i1;
                        stage[row_local * 2 + warp_n] = t;
                    }
                }
            }
            __syncthreads();
            if (tid < 256) {
                Top2 a = stage[tid * 2 + 0];
                Top2 b = stage[tid * 2 + 1];
                top2_insert(b.v0, b.i0, a.v0, a.i0, a.v1, a.i1);
                top2_insert(b.v1, b.i1, a.v0, a.i0, a.v1, a.i1);
                g_part[(size_t)tile * B_DIM + (mbase + tid)] = a;
            }
            __syncthreads();

            #pragma unroll
            for (int mt = 0; mt < 2; mt++)
                #pragma unroll
                for (int nt = 0; nt < 8; nt++)
                    #pragma unroll
                    for (int cc = 0; cc < 4; cc++) acc[mt][nt][cc] = 0.0f;
        }
    }
}

// ---------------- kernel 4: merge partials -> top-4, exact fp32 rescore -----
__global__ __launch_bounds__(256) void reduce_rescore_kernel(
    const float* __restrict__ input, const float* __restrict__ target,
    const float* __restrict__ veclist) {
    const int warp = (int)((blockIdx.x * blockDim.x + threadIdx.x) >> 5);
    const int lane = threadIdx.x & 31;
    if (warp >= B_DIM) return;
    const int row = warp;

    float v[4] = {-1e30f, -1e30f, -1e30f, -1e30f};
    int   ix[4] = {0, 0, 0, 0};
    for (int s = lane; s < NUM_VT; s += 32) {
        Top2 p = g_part[(size_t)s * B_DIM + row];
        if (p.i0 >= 0) top4_insert(p.v0, p.i0, v, ix);
        if (p.i1 >= 0) top4_insert(p.v1, p.i1, v, ix);
    }
    #pragma unroll
    for (int o = 16; o > 0; o >>= 1) {
        #pragma unroll
        for (int r = 0; r < 4; r++) {
            float ov = __shfl_xor_sync(0xFFFFFFFFu, v[r], o);
            int   oi = __shfl_xor_sync(0xFFFFFFFFu, ix[r], o);
            top4_insert(ov, oi, v, ix);
        }
    }
    // broadcast lane0's candidate set
    #pragma unroll
    for (int r = 0; r < 4; r++) {
        v[r]  = __shfl_sync(0xFFFFFFFFu, v[r], 0);
        ix[r] = __shfl_sync(0xFFFFFFFFu, ix[r], 0);
    }

    // exact fp32 rescore of the 4 candidates
    const float* x = input  + (size_t)row * D_DIM;
    const float* t = target + (size_t)row * D_DIM;
    const float* cand[4];
    #pragma unroll
    for (int r = 0; r < 4; r++) cand[r] = veclist + (size_t)ix[r] * D_DIM;

    float dot[4] = {0, 0, 0, 0}, nrm[4] = {0, 0, 0, 0};
    bool eq[4] = {true, true, true, true};
    for (int k = lane; k < D_DIM; k += 32) {
        float xi = x[k], ti = t[k];
        #pragma unroll
        for (int r = 0; r < 4; r++) {
            float a = cand[r][k];
            dot[r] = fmaf(xi, a, dot[r]);
            nrm[r] = fmaf(a, a, nrm[r]);
            eq[r] = eq[r] && (a == ti);
        }
    }
    #pragma unroll
    for (int o = 16; o > 0; o >>= 1) {
        #pragma unroll
        for (int r = 0; r < 4; r++) {
            dot[r] += __shfl_xor_sync(0xFFFFFFFFu, dot[r], o);
            nrm[r] += __shfl_xor_sync(0xFFFFFFFFu, nrm[r], o);
        }
    }
    #pragma unroll
    for (int r = 0; r < 4; r++) eq[r] = __all_sync(0xFFFFFFFFu, eq[r]);

    if (lane == 0) {
        const float nin = g_norm_in[row];
        float s[4];
        #pragma unroll
        for (int r = 0; r < 4; r++)
            s[r] = dot[r] / (nin * fmaxf(sqrtf(nrm[r]), EPSF));

        // exact top-2 among the 4 candidates
        int b0 = 0, b1 = -1;
        #pragma unroll
        for (int r = 1; r < 4; r++) if (s[r] > s[b0]) b0 = r;
        float sb1 = -1e30f;
        #pragma unroll
        for (int r = 0; r < 4; r++)
            if (r != b0 && s[r] > sb1) { sb1 = s[r]; b1 = r; }

        const float sneg = eq[b0] ? s[b1] : s[b0];
        const float dneg = sqrtf(fmaxf(2.0f * (1.0f - sneg), 1e-12f));
        const float margin = GAMMAF + g_dpos[row] - dneg;
        g_margin[row] = 2.0f * fmaxf(margin, 0.0f);
    }
}

// ---------------- kernel 5: deterministic final reduction -------------------
__global__ __launch_bounds__(256) void final_sum_kernel(float* __restrict__ out) {
    __shared__ float s[256];
    float acc = 0.0f;
    for (int i = threadIdx.x; i < B_DIM; i += 256) acc += g_margin[i];
    s[threadIdx.x] = acc;
    __syncthreads();
    for (int st = 128; st > 0; st >>= 1) {
        if (threadIdx.x < st) s[threadIdx.x] += s[threadIdx.x + st];
        __syncthreads();
    }
    if (threadIdx.x == 0) out[0] = s[0] * (1.0f / (float)B_DIM);
}

// ---------------- launcher ---------------------------------------------------
extern "C" void kernel_launch(void* const* d_in, const int* in_sizes, int n_in,
                              void* d_out, int out_size) {
    (void)in_sizes; (void)n_in; (void)out_size;
    const float* input   = (const float*)d_in[0];
    const float* target  = (const float*)d_in[1];
    const float* veclist = (const float*)d_in[2];
    float* out = (float*)d_out;

    cudaFuncSetAttribute(gemm_top2_kernel,
                         cudaFuncAttributeMaxDynamicSharedMemorySize, SMEM_TOTAL);

    prep_input_kernel<<<B_DIM, 128>>>(input, target);
    prep_vec_kernel<<<V_PAD, 128>>>(veclist);

    dim3 grid(V_GROUPS, M_BLOCKS);
    gemm_top2_kernel<<<grid, 512, SMEM_TOTAL>>>();

    reduce_rescore_kernel<<<(B_DIM * 32) / 256, 256>>>(input, target, veclist);
    final_sum_kernel<<<1, 256>>>(out);
}